// round 1
// baseline (speedup 1.0000x reference)
#include <cuda_runtime.h>

#define NTOK   16384
#define DIM    2048
#define NE     64
#define KTOP   8
#define ALPHA_C 0.001f

#define TM     128            // tokens per block
#define KC     16             // k-chunk
#define KPAD   (KC + 4)       // bank-stagger pad, keeps 16B alignment
#define NBLK   (NTOK / TM)    // 128 blocks
#define NCHUNK (DIM / KC)     // 128 chunks

// Per-block partials for the aux loss (deterministic fixed-order reduce later).
__device__ float g_cnt_part[NBLK][NE];
__device__ float g_prob_part[NBLK][NE];

struct Tiles {
    float hs[2][TM][KPAD];    // [buf][token][k]   20.5 KB
    float ws[2][NE][KPAD];    // [buf][expert][k]  10.25 KB
};
union Smem {
    Tiles t;
    float logits[TM][NE + 1]; // 33.3 KB, reused after GEMM
};

__global__ __launch_bounds__(256, 1)
void gate_kernel(const float* __restrict__ H, const float* __restrict__ W,
                 float* __restrict__ out)
{
    __shared__ Smem u;
    __shared__ float rinv[TM];
    __shared__ float sm_cnt[NE];
    __shared__ float pr[4][NE];

    const int tid = threadIdx.x;
    const int blk = blockIdx.x;
    const int er  = tid & 15;   // expert group: experts er*4 .. er*4+3
    const int tr  = tid >> 4;   // token  group: tokens  tr*8 .. tr*8+7

    if (tid < NE) sm_cnt[tid] = 0.f;

    float acc[8][4];
#pragma unroll
    for (int i = 0; i < 8; i++)
#pragma unroll
        for (int j = 0; j < 4; j++) acc[i][j] = 0.f;

    const float* Hb = H + (size_t)blk * TM * DIM;

    // global->smem loader mapping (float4 granularity)
    const int hrow0 = tid >> 2;                 // rows 0..63
    const int hrow1 = (tid + 256) >> 2;         // rows 64..127
    const int hc    = (tid & 3) * 4;            // k-offset within chunk
    const int wrow  = tid >> 2;                 // experts 0..63
    const int wc    = (tid & 3) * 4;

    // prologue: chunk 0 -> buf 0 (loop-top barrier publishes it)
    {
        float4 a = *(const float4*)(Hb + (size_t)hrow0 * DIM + hc);
        float4 b = *(const float4*)(Hb + (size_t)hrow1 * DIM + hc);
        float4 w = *(const float4*)(W  + (size_t)wrow  * DIM + wc);
        *(float4*)&u.t.hs[0][hrow0][hc] = a;
        *(float4*)&u.t.hs[0][hrow1][hc] = b;
        *(float4*)&u.t.ws[0][wrow][wc]  = w;
    }

    for (int c = 0; c < NCHUNK; c++) {
        const int b = c & 1;
        float4 hn0, hn1, wn;
        const bool more = (c + 1 < NCHUNK);
        if (more) {
            const int kb = (c + 1) * KC;
            hn0 = *(const float4*)(Hb + (size_t)hrow0 * DIM + kb + hc);
            hn1 = *(const float4*)(Hb + (size_t)hrow1 * DIM + kb + hc);
            wn  = *(const float4*)(W  + (size_t)wrow  * DIM + kb + wc);
        }
        __syncthreads();  // prev STS to buf b visible; prev compute on buf b^1 done
#pragma unroll
        for (int k4 = 0; k4 < KC; k4 += 4) {
            float4 hv[8], wv[4];
#pragma unroll
            for (int i = 0; i < 8; i++)
                hv[i] = *(const float4*)&u.t.hs[b][tr * 8 + i][k4];
#pragma unroll
            for (int j = 0; j < 4; j++)
                wv[j] = *(const float4*)&u.t.ws[b][er * 4 + j][k4];
#pragma unroll
            for (int i = 0; i < 8; i++)
#pragma unroll
                for (int j = 0; j < 4; j++) {
                    acc[i][j] = fmaf(hv[i].x, wv[j].x, acc[i][j]);
                    acc[i][j] = fmaf(hv[i].y, wv[j].y, acc[i][j]);
                    acc[i][j] = fmaf(hv[i].z, wv[j].z, acc[i][j]);
                    acc[i][j] = fmaf(hv[i].w, wv[j].w, acc[i][j]);
                }
        }
        if (more) {
            *(float4*)&u.t.hs[b ^ 1][hrow0][hc] = hn0;
            *(float4*)&u.t.hs[b ^ 1][hrow1][hc] = hn1;
            *(float4*)&u.t.ws[b ^ 1][wrow][wc]  = wn;
        }
    }
    __syncthreads();  // all compute done before union is repurposed

    // -------- logits -> smem --------
#pragma unroll
    for (int i = 0; i < 8; i++)
#pragma unroll
        for (int j = 0; j < 4; j++)
            u.logits[tr * 8 + i][er * 4 + j] = acc[i][j];
    __syncthreads();

    // -------- per-token softmax + top-8 (one thread per token) --------
    if (tid < TM) {
        float m = -1e30f;
        for (int e = 0; e < NE; e++) m = fmaxf(m, u.logits[tid][e]);

        float s = 0.f;
        float val[KTOP];
        int   idx[KTOP];
#pragma unroll
        for (int j = 0; j < KTOP; j++) { val[j] = -1.f; idx[j] = 0; }

        for (int e = 0; e < NE; e++) {
            float ex = __expf(u.logits[tid][e] - m);
            u.logits[tid][e] = ex;   // stash exp for mean-prob pass
            s += ex;
            // sorted-descending insertion; strict > keeps earlier index on ties
            float nv = ex; int ni = e;
#pragma unroll
            for (int j = 0; j < KTOP; j++) {
                if (nv > val[j]) {
                    float tv = val[j]; val[j] = nv; nv = tv;
                    int   ti = idx[j]; idx[j] = ni; ni = ti;
                }
            }
        }
        rinv[tid] = 1.f / s;

        float ts = 0.f;
#pragma unroll
        for (int j = 0; j < KTOP; j++) ts += val[j];
        const float tinv = 1.f / ts;

        const int gt = blk * TM + tid;
        float* ow = out + (size_t)gt * KTOP;
        float* oi = out + (size_t)NTOK * KTOP + (size_t)gt * KTOP;
#pragma unroll
        for (int j = 0; j < KTOP; j++) {
            ow[j] = val[j] * tinv;     // normalized top-k weight
            oi[j] = (float)idx[j];     // index as float (output dtype fp32)
            atomicAdd(&sm_cnt[idx[j]], 1.f);  // integer counts: order-exact
        }
    }
    __syncthreads();

    // -------- per-block mean-prob partial: sum_t exp[t][e]/rowsum[t] --------
    {
        const int e = tid & 63;
        const int p = tid >> 6;   // 0..3, 32 tokens each
        float sacc = 0.f;
        for (int t = p * 32; t < p * 32 + 32; t++)
            sacc += u.logits[t][e] * rinv[t];
        pr[p][e] = sacc;
    }
    __syncthreads();
    if (tid < NE) {
        g_prob_part[blk][tid] = pr[0][tid] + pr[1][tid] + pr[2][tid] + pr[3][tid];
        g_cnt_part[blk][tid]  = sm_cnt[tid];
    }
}

__global__ void finalize_kernel(float* __restrict__ out, int out_size)
{
    __shared__ float red[NE];
    const int e = threadIdx.x;   // 64 threads
    float c = 0.f, pm = 0.f;
    for (int b = 0; b < NBLK; b++) {   // fixed order -> deterministic
        c  += g_cnt_part[b][e];
        pm += g_prob_part[b][e];
    }
    const float v = (c / (float)(NTOK * KTOP)) * (pm / (float)NTOK);
    red[e] = v;
    __syncthreads();
    if (e == 0) {
        float s = 0.f;
        for (int i = 0; i < NE; i++) s += red[i];
        const int pos = NTOK * KTOP * 2;
        if (pos < out_size) out[pos] = ALPHA_C * (float)NE * s;
    }
}

extern "C" void kernel_launch(void* const* d_in, const int* in_sizes, int n_in,
                              void* d_out, int out_size)
{
    const float* H = (const float*)d_in[0];   // hidden_states (16384, 2048) fp32
    const float* W = (const float*)d_in[1];   // weight (64, 2048) fp32
    float* out = (float*)d_out;

    gate_kernel<<<NBLK, 256>>>(H, W, out);
    finalize_kernel<<<1, NE>>>(out, out_size);
}

// round 3
// speedup vs baseline: 1.6500x; 1.6500x over previous
#include <cuda_runtime.h>

#define NTOK   16384
#define DIM    2048
#define NE     64
#define KTOP   8
#define ALPHA_C 0.001f

#define TM     128            // tokens per block
#define KC     16             // k-chunk
#define KPAD   (KC + 4)       // W tile pitch: lane-stride 20 words -> conflict-free reads
#define P2     (2*KC + 4)     // H pair-tile pitch (36 floats): 16B-aligned float4 rows
#define NBLK   (NTOK / TM)    // 128 blocks
#define NCHUNK (DIM / KC)     // 128 chunks

// Per-block partials for aux loss (deterministic fixed-order reduce in last block).
__device__ float g_cnt_part[NBLK][NE];
__device__ float g_prob_part[NBLK][NE];
__device__ unsigned int g_sync = 0;   // atomicInc wraps to 0 each launch -> graph-replay safe

struct Tiles {
    float hs2[2][TM / 2][P2];  // token-pair interleaved: element [tp][2k + (t&1)]
    float ws[2][NE][KPAD];     // [expert][k]
};
union Smem {
    Tiles t;
    float logits[TM][NE + 1];  // reused after GEMM
};

typedef unsigned long long u64;

// lane-wise fma.rn: each 32-bit lane rounds exactly like scalar fmaf
__device__ __forceinline__ void ffma2(u64& d, u64 a, u64 b) {
    asm("fma.rn.f32x2 %0, %1, %2, %3;" : "=l"(d) : "l"(a), "l"(b), "l"(d));
}
__device__ __forceinline__ u64 pack2(float x) {   // {x, x}
    u64 r; asm("mov.b64 %0, {%1, %1};" : "=l"(r) : "f"(x)); return r;
}
__device__ __forceinline__ void unpack2(u64 v, float& lo, float& hi) {
    unsigned int a, b;
    asm("mov.b64 {%0, %1}, %2;" : "=r"(a), "=r"(b) : "l"(v));
    lo = __uint_as_float(a); hi = __uint_as_float(b);
}

__device__ __forceinline__ void sts_hpair(float (*hs2)[P2], int row, int kbase, float4 v) {
    // scatter one token row's float4 into the pair-interleaved tile
    const int tp = row >> 1, lane = row & 1;
    hs2[tp][2 * (kbase + 0) + lane] = v.x;
    hs2[tp][2 * (kbase + 1) + lane] = v.y;
    hs2[tp][2 * (kbase + 2) + lane] = v.z;
    hs2[tp][2 * (kbase + 3) + lane] = v.w;
}

__global__ __launch_bounds__(256, 1)
void gate_kernel(const float* __restrict__ H, const float* __restrict__ W,
                 float* __restrict__ out, int out_size)
{
    __shared__ Smem u;
    __shared__ float rinv[TM];
    __shared__ float sm_cnt[NE];
    __shared__ float pr[4][NE];
    __shared__ float rc[4][NE], rp[4][NE];
    __shared__ unsigned int is_last;

    const int tid = threadIdx.x;
    const int blk = blockIdx.x;
    const int er  = tid & 15;   // experts: er, er+16, er+32, er+48
    const int tr  = tid >> 4;   // token pairs tr*4 .. tr*4+3  (tokens tr*8..tr*8+7)

    if (tid < NE) sm_cnt[tid] = 0.f;

    // acc2[i][j]: lanes = tokens {2*(tr*4+i), +1}, expert er+16j.
    // Each lane accumulates k sequentially 0..2047 -> bit-identical to scalar fmaf chain.
    u64 acc2[4][4];
#pragma unroll
    for (int i = 0; i < 4; i++)
#pragma unroll
        for (int j = 0; j < 4; j++) acc2[i][j] = 0ull;

    const float* Hb = H + (size_t)blk * TM * DIM;

    const int hrow0 = tid >> 2;                 // rows 0..63
    const int hrow1 = (tid + 256) >> 2;         // rows 64..127
    const int hc    = (tid & 3) * 4;
    const int wrow  = tid >> 2;
    const int wc    = (tid & 3) * 4;

    // prologue: chunk 0 -> buf 0
    {
        float4 a = *(const float4*)(Hb + (size_t)hrow0 * DIM + hc);
        float4 b = *(const float4*)(Hb + (size_t)hrow1 * DIM + hc);
        float4 w = *(const float4*)(W  + (size_t)wrow  * DIM + wc);
        sts_hpair(u.t.hs2[0], hrow0, hc, a);
        sts_hpair(u.t.hs2[0], hrow1, hc, b);
        *(float4*)&u.t.ws[0][wrow][wc] = w;
    }

    for (int c = 0; c < NCHUNK; c++) {
        const int b = c & 1;
        float4 hn0, hn1, wn;
        const bool more = (c + 1 < NCHUNK);
        if (more) {
            const int kb = (c + 1) * KC;
            hn0 = *(const float4*)(Hb + (size_t)hrow0 * DIM + kb + hc);
            hn1 = *(const float4*)(Hb + (size_t)hrow1 * DIM + kb + hc);
            wn  = *(const float4*)(W  + (size_t)wrow  * DIM + kb + wc);
        }
        __syncthreads();
#pragma unroll
        for (int k4 = 0; k4 < KC; k4 += 4) {
            ulonglong2 h01[4], h23[4];
#pragma unroll
            for (int i = 0; i < 4; i++) {
                const float* p = &u.t.hs2[b][tr * 4 + i][2 * k4];
                h01[i] = *(const ulonglong2*)p;        // pairs for k4, k4+1
                h23[i] = *(const ulonglong2*)(p + 4);  // pairs for k4+2, k4+3
            }
#pragma unroll
            for (int j = 0; j < 4; j++) {
                float4 w = *(const float4*)&u.t.ws[b][er + 16 * j][k4];
                u64 w0 = pack2(w.x), w1 = pack2(w.y), w2 = pack2(w.z), w3 = pack2(w.w);
#pragma unroll
                for (int i = 0; i < 4; i++) {
                    ffma2(acc2[i][j], h01[i].x, w0);
                    ffma2(acc2[i][j], h01[i].y, w1);
                    ffma2(acc2[i][j], h23[i].x, w2);
                    ffma2(acc2[i][j], h23[i].y, w3);
                }
            }
        }
        if (more) {
            sts_hpair(u.t.hs2[b ^ 1], hrow0, hc, hn0);
            sts_hpair(u.t.hs2[b ^ 1], hrow1, hc, hn1);
            *(float4*)&u.t.ws[b ^ 1][wrow][wc] = wn;
        }
    }
    __syncthreads();  // all compute done before union is repurposed

    // -------- logits -> smem --------
#pragma unroll
    for (int i = 0; i < 4; i++)
#pragma unroll
        for (int j = 0; j < 4; j++) {
            float lo, hi;
            unpack2(acc2[i][j], lo, hi);
            const int t0 = 2 * (tr * 4 + i);
            u.logits[t0][er + 16 * j]     = lo;
            u.logits[t0 + 1][er + 16 * j] = hi;
        }
    __syncthreads();

    // -------- per-token softmax + top-8 (one thread per token) --------
    if (tid < TM) {
        float m = -1e30f;
        for (int e = 0; e < NE; e++) m = fmaxf(m, u.logits[tid][e]);

        float s = 0.f;
        float val[KTOP];
        int   idx[KTOP];
#pragma unroll
        for (int j = 0; j < KTOP; j++) { val[j] = -1.f; idx[j] = 0; }

        for (int e = 0; e < NE; e++) {
            float ex = __expf(u.logits[tid][e] - m);
            u.logits[tid][e] = ex;   // stash exp for mean-prob pass
            s += ex;
            float nv = ex; int ni = e;
#pragma unroll
            for (int j = 0; j < KTOP; j++) {
                if (nv > val[j]) {
                    float tv = val[j]; val[j] = nv; nv = tv;
                    int   ti = idx[j]; idx[j] = ni; ni = ti;
                }
            }
        }
        rinv[tid] = 1.f / s;

        float ts = 0.f;
#pragma unroll
        for (int j = 0; j < KTOP; j++) ts += val[j];
        const float tinv = 1.f / ts;

        const int gt = blk * TM + tid;
        float* ow = out + (size_t)gt * KTOP;
        float* oi = out + (size_t)NTOK * KTOP + (size_t)gt * KTOP;
#pragma unroll
        for (int j = 0; j < KTOP; j++) {
            ow[j] = val[j] * tinv;
            oi[j] = (float)idx[j];
            atomicAdd(&sm_cnt[idx[j]], 1.f);  // integer counts: order-exact
        }
    }
    __syncthreads();

    // -------- per-block mean-prob partial --------
    {
        const int e = tid & 63;
        const int p = tid >> 6;
        float sacc = 0.f;
        for (int t = p * 32; t < p * 32 + 32; t++)
            sacc += u.logits[t][e] * rinv[t];
        pr[p][e] = sacc;
    }
    __syncthreads();
    if (tid < NE) {
        g_prob_part[blk][tid] = pr[0][tid] + pr[1][tid] + pr[2][tid] + pr[3][tid];
        g_cnt_part[blk][tid]  = sm_cnt[tid];
    }

    // -------- last block finalizes the aux loss (no second launch) --------
    __threadfence();
    if (tid == 0)
        is_last = (atomicInc(&g_sync, NBLK - 1) == NBLK - 1);
    __syncthreads();
    if (is_last) {
        const int e = tid & 63;
        const int p = tid >> 6;       // 4 parts x 32 blocks, fixed order
        float c = 0.f, pm = 0.f;
        for (int b = p * 32; b < p * 32 + 32; b++) {
            c  += g_cnt_part[b][e];
            pm += g_prob_part[b][e];
        }
        rc[p][e] = c; rp[p][e] = pm;
        __syncthreads();
        if (tid == 0) {
            float s = 0.f;
            for (int e2 = 0; e2 < NE; e2++) {
                float C = rc[0][e2] + rc[1][e2] + rc[2][e2] + rc[3][e2];
                float P = rp[0][e2] + rp[1][e2] + rp[2][e2] + rp[3][e2];
                s += (C / (float)(NTOK * KTOP)) * (P / (float)NTOK);
            }
            const int pos = NTOK * KTOP * 2;
            if (pos < out_size) out[pos] = ALPHA_C * (float)NE * s;
        }
    }
}

extern "C" void kernel_launch(void* const* d_in, const int* in_sizes, int n_in,
                              void* d_out, int out_size)
{
    const float* H = (const float*)d_in[0];   // hidden_states (16384, 2048) fp32
    const float* W = (const float*)d_in[1];   // weight (64, 2048) fp32
    float* out = (float*)d_out;

    gate_kernel<<<NBLK, 256>>>(H, W, out, out_size);
}